// round 1
// baseline (speedup 1.0000x reference)
#include <cuda_runtime.h>

#define N   128
#define N3  (N*N*N)
#define PYR 299593   // 64^3+32^3+16^3+8^3+4^3+2^3+1

// Scratch: BU BV BW U1 V1 W1 B R0 P1 (9 x N3) + residual pyramid + correction pyramid
__device__ float g_scratch[9 * (size_t)N3 + 2 * (size_t)PYR];

static __device__ __forceinline__ int cl(int x) { return x < 0 ? 0 : (x > N - 1 ? N - 1 : x); }
static __device__ __forceinline__ int ix(int d, int h, int w) { return (d << 14) + (h << 7) + w; }

// ---------------------------------------------------------------------------
// Predictor: b_* = solid( usol + 0.5*dt*(lap - adv) - dt*grad(p) )
// usol = values_* * f, f = 1/(1+dt*sigma); u-field has inlet BC (=1) at w-1<0.
// ---------------------------------------------------------------------------
__global__ void __launch_bounds__(512) k_predictor(
    const float* __restrict__ U, const float* __restrict__ V, const float* __restrict__ W_,
    const float* __restrict__ P, const float* __restrict__ SG, const float* __restrict__ DT,
    float* __restrict__ BU, float* __restrict__ BV, float* __restrict__ BW)
{
    const int w = threadIdx.x;
    const int h = (blockIdx.y << 2) + threadIdx.y;
    const int d = blockIdx.z;
    const float dt = DT[0];

    const int c  = ix(d, h, w);
    const int iW = ix(d, h, cl(w - 1)), iE = ix(d, h, cl(w + 1));
    const int iS = ix(d, cl(h - 1), w), iN = ix(d, cl(h + 1), w);
    const int iB = ix(cl(d - 1), h, w), iT = ix(cl(d + 1), h, w);

    const float fc = 1.f / (1.f + dt * SG[c]);
    const float fW = 1.f / (1.f + dt * SG[iW]);
    const float fE = 1.f / (1.f + dt * SG[iE]);
    const float fS = 1.f / (1.f + dt * SG[iS]);
    const float fN = 1.f / (1.f + dt * SG[iN]);
    const float fB = 1.f / (1.f + dt * SG[iB]);
    const float fT = 1.f / (1.f + dt * SG[iT]);

    const float uc = U[c] * fc, vc = V[c] * fc, wc = W_[c] * fc;

    // u-field (inlet BC ub=1 at w==0 west halo)
    float uW = (w == 0) ? 1.0f : U[iW] * fW;
    float uE = U[iE] * fE, uS = U[iS] * fS, uN = U[iN] * fN, uB = U[iB] * fB, uT = U[iT] * fT;
    float lap_u = uW + uE + uS + uN + uB + uT - 6.f * uc;
    float ax_u = 0.5f * (uE - uW), ay_u = 0.5f * (uN - uS), az_u = 0.5f * (uT - uB);

    // v-field
    float vW = V[iW] * fW, vE = V[iE] * fE, vS = V[iS] * fS, vN = V[iN] * fN, vB = V[iB] * fB, vT = V[iT] * fT;
    float lap_v = vW + vE + vS + vN + vB + vT - 6.f * vc;
    float ax_v = 0.5f * (vE - vW), ay_v = 0.5f * (vN - vS), az_v = 0.5f * (vT - vB);

    // w-field
    float wW = W_[iW] * fW, wE = W_[iE] * fE, wS = W_[iS] * fS, wN = W_[iN] * fN, wB = W_[iB] * fB, wT = W_[iT] * fT;
    float lap_w = wW + wE + wS + wN + wB + wT - 6.f * wc;
    float ax_w = 0.5f * (wE - wW), ay_w = 0.5f * (wN - wS), az_w = 0.5f * (wT - wB);

    const float pW = P[iW], pE = P[iE], pS = P[iS], pN = P[iN], pB = P[iB], pT = P[iT];

    BU[c] = (uc + 0.5f * dt * (lap_u - uc * ax_u - vc * ay_u - wc * az_u) - dt * 0.5f * (pE - pW)) * fc;
    BV[c] = (vc + 0.5f * dt * (lap_v - uc * ax_v - vc * ay_v - wc * az_v) - dt * 0.5f * (pN - pS)) * fc;
    BW[c] = (wc + 0.5f * dt * (lap_w - uc * ax_w - vc * ay_w - wc * az_w) - dt * 0.5f * (pT - pB)) * fc;
}

// ---------------------------------------------------------------------------
// Corrector: u1 = solid( usol + dt*(lap(b) - b.grad(b)) - dt*grad(p) )
// ---------------------------------------------------------------------------
__global__ void __launch_bounds__(512) k_corrector(
    const float* __restrict__ BU, const float* __restrict__ BV, const float* __restrict__ BW,
    const float* __restrict__ U, const float* __restrict__ V, const float* __restrict__ W_,
    const float* __restrict__ P, const float* __restrict__ SG, const float* __restrict__ DT,
    float* __restrict__ U1, float* __restrict__ V1, float* __restrict__ W1)
{
    const int w = threadIdx.x;
    const int h = (blockIdx.y << 2) + threadIdx.y;
    const int d = blockIdx.z;
    const float dt = DT[0];

    const int c  = ix(d, h, w);
    const int iW = ix(d, h, cl(w - 1)), iE = ix(d, h, cl(w + 1));
    const int iS = ix(d, cl(h - 1), w), iN = ix(d, cl(h + 1), w);
    const int iB = ix(cl(d - 1), h, w), iT = ix(cl(d + 1), h, w);

    const float fc = 1.f / (1.f + dt * SG[c]);
    const float uc = U[c] * fc, vc = V[c] * fc, wc2 = W_[c] * fc;
    const float buC = BU[c], bvC = BV[c], bwC = BW[c];

    float aW = (w == 0) ? 1.0f : BU[iW];
    float aE = BU[iE], aS = BU[iS], aN = BU[iN], aB = BU[iB], aT = BU[iT];
    float lap_a = aW + aE + aS + aN + aB + aT - 6.f * buC;
    float ax_a = 0.5f * (aE - aW), ay_a = 0.5f * (aN - aS), az_a = 0.5f * (aT - aB);

    float bW = BV[iW], bE = BV[iE], bS = BV[iS], bN = BV[iN], bB = BV[iB], bT = BV[iT];
    float lap_b = bW + bE + bS + bN + bB + bT - 6.f * bvC;
    float ax_b = 0.5f * (bE - bW), ay_b = 0.5f * (bN - bS), az_b = 0.5f * (bT - bB);

    float cW = BW[iW], cE = BW[iE], cS = BW[iS], cN = BW[iN], cB = BW[iB], cT = BW[iT];
    float lap_c = cW + cE + cS + cN + cB + cT - 6.f * bwC;
    float ax_c = 0.5f * (cE - cW), ay_c = 0.5f * (cN - cS), az_c = 0.5f * (cT - cB);

    const float pW = P[iW], pE = P[iE], pS = P[iS], pN = P[iN], pB = P[iB], pT = P[iT];

    U1[c] = (uc  + dt * (lap_a - buC * ax_a - bvC * ay_a - bwC * az_a) - dt * 0.5f * (pE - pW)) * fc;
    V1[c] = (vc  + dt * (lap_b - buC * ax_b - bvC * ay_b - bwC * az_b) - dt * 0.5f * (pN - pS)) * fc;
    W1[c] = (wc2 + dt * (lap_c - buC * ax_c - bvC * ay_c - bwC * az_c) - dt * 0.5f * (pT - pB)) * fc;
}

// b = -(div velocity)/dt  (u-field with inlet BC)
__global__ void __launch_bounds__(512) k_div(
    const float* __restrict__ U1, const float* __restrict__ V1, const float* __restrict__ W1,
    const float* __restrict__ DT, float* __restrict__ B)
{
    const int w = threadIdx.x;
    const int h = (blockIdx.y << 2) + threadIdx.y;
    const int d = blockIdx.z;
    const float dt = DT[0];
    const int c = ix(d, h, w);
    float uW = (w == 0) ? 1.0f : U1[ix(d, h, w - 1)];
    float uE = U1[ix(d, h, cl(w + 1))];
    float vS = V1[ix(d, cl(h - 1), w)], vN = V1[ix(d, cl(h + 1), w)];
    float wB = W1[ix(cl(d - 1), h, w)], wT = W1[ix(cl(d + 1), h, w)];
    B[c] = -(0.5f * (uE - uW) + 0.5f * (vN - vS) + 0.5f * (wT - wB)) / dt;
}

// r0 = A(edge_pad(p)) - b
__global__ void __launch_bounds__(512) k_resid(
    const float* __restrict__ P, const float* __restrict__ B, float* __restrict__ R0)
{
    const int w = threadIdx.x;
    const int h = (blockIdx.y << 2) + threadIdx.y;
    const int d = blockIdx.z;
    const int c = ix(d, h, w);
    float pc = P[c];
    float s = P[ix(d, h, cl(w - 1))] + P[ix(d, h, cl(w + 1))]
            + P[ix(d, cl(h - 1), w)] + P[ix(d, cl(h + 1), w)]
            + P[ix(cl(d - 1), h, w)] + P[ix(cl(d + 1), h, w)];
    R0[c] = (s - 6.f * pc) - B[c];
}

// stride-2 restriction (average of 2^3 block)
__global__ void k_restrict(const float* __restrict__ src, float* __restrict__ dst, int ms)
{
    const int md = ms >> 1;
    const int n = md * md * md;
    const int t = blockIdx.x * blockDim.x + threadIdx.x;
    if (t >= n) return;
    const int w = t % md, h = (t / md) % md, d = t / (md * md);
    const int b0 = ((2 * d) * ms + 2 * h) * ms + 2 * w;
    const int ms2 = ms * ms;
    float s = src[b0] + src[b0 + 1] + src[b0 + ms] + src[b0 + ms + 1]
            + src[b0 + ms2] + src[b0 + ms2 + 1] + src[b0 + ms2 + ms] + src[b0 + ms2 + ms + 1];
    dst[t] = 0.125f * s;
}

// MG level: win(x)=cprev[x>>1] (prol fused, zero_pad outside), Jacobi step
__global__ void k_mglevel(const float* __restrict__ cprev, const float* __restrict__ r,
                          float* __restrict__ out, int m)
{
    const int n = m * m * m;
    const int t = blockIdx.x * blockDim.x + threadIdx.x;
    if (t >= n) return;
    const int w = t % m, h = (t / m) % m, d = t / (m * m);
    const int mc = m >> 1;

    auto rd = [&](int dd, int hh, int ww) -> float {
        if (dd < 0 || dd >= m || hh < 0 || hh >= m || ww < 0 || ww >= m) return 0.f;
        if (!cprev) return 0.f;
        return cprev[((dd >> 1) * mc + (hh >> 1)) * mc + (ww >> 1)];
    };
    float wc = rd(d, h, w);
    float lap = rd(d - 1, h, w) + rd(d + 1, h, w) + rd(d, h - 1, w) + rd(d, h + 1, w)
              + rd(d, h, w - 1) + rd(d, h, w + 1) - 6.f * wc;
    out[t] = wc - lap / (-6.f) + r[t] / (-6.f);
}

// p_new = p_old - prol(c1) - r0/diag ; optionally emit wmg = prol(c1)
__global__ void __launch_bounds__(512) k_pupdate(
    const float* __restrict__ pold, const float* __restrict__ c1, const float* __restrict__ r0,
    float* __restrict__ pnew, float* __restrict__ wmg_out)
{
    const int w = threadIdx.x;
    const int h = (blockIdx.y << 2) + threadIdx.y;
    const int d = blockIdx.z;
    const int c = ix(d, h, w);
    const float wmg = c1[((d >> 1) * 64 + (h >> 1)) * 64 + (w >> 1)];
    pnew[c] = pold[c] - wmg - r0[c] / (-6.f);
    if (wmg_out) wmg_out[c] = wmg;
}

// final: u = solid(u1 - dt*grad(p_final))
__global__ void __launch_bounds__(512) k_final(
    const float* __restrict__ U1, const float* __restrict__ V1, const float* __restrict__ W1,
    const float* __restrict__ Pf, const float* __restrict__ SG, const float* __restrict__ DT,
    float* __restrict__ OU, float* __restrict__ OV, float* __restrict__ OW)
{
    const int w = threadIdx.x;
    const int h = (blockIdx.y << 2) + threadIdx.y;
    const int d = blockIdx.z;
    const float dt = DT[0];
    const int c = ix(d, h, w);
    const float fc = 1.f / (1.f + dt * SG[c]);
    float pW = Pf[ix(d, h, cl(w - 1))], pE = Pf[ix(d, h, cl(w + 1))];
    float pS = Pf[ix(d, cl(h - 1), w)], pN = Pf[ix(d, cl(h + 1), w)];
    float pB = Pf[ix(cl(d - 1), h, w)], pT = Pf[ix(cl(d + 1), h, w)];
    OU[c] = (U1[c] - dt * 0.5f * (pE - pW)) * fc;
    OV[c] = (V1[c] - dt * 0.5f * (pN - pS)) * fc;
    OW[c] = (W1[c] - dt * 0.5f * (pT - pB)) * fc;
}

__global__ void k_copyr(const float* __restrict__ src, float* __restrict__ dst)
{
    dst[0] = src[0];
}

// ---------------------------------------------------------------------------
extern "C" void kernel_launch(void* const* d_in, const int* in_sizes, int n_in,
                              void* d_out, int out_size)
{
    const float* U  = (const float*)d_in[0];
    const float* V  = (const float*)d_in[1];
    const float* W_ = (const float*)d_in[2];
    const float* P  = (const float*)d_in[3];
    const float* SG = (const float*)d_in[4];
    const float* DT = (const float*)d_in[5];
    // ub=1, Re=1, iteration=2, nlevel=9: fixed structural constants of this problem.

    float* out   = (float*)d_out;
    float* o_u   = out;
    float* o_v   = out + (size_t)N3;
    float* o_w   = out + 2 * (size_t)N3;
    float* o_p   = out + 3 * (size_t)N3;
    float* o_wmg = out + 4 * (size_t)N3;
    float* o_r   = out + 5 * (size_t)N3;

    float* S = nullptr;
    cudaGetSymbolAddress((void**)&S, g_scratch);
    float* BU = S;
    float* BV = S + (size_t)N3;
    float* BW = S + 2 * (size_t)N3;
    float* U1 = S + 3 * (size_t)N3;
    float* V1 = S + 4 * (size_t)N3;
    float* W1 = S + 5 * (size_t)N3;
    float* B  = S + 6 * (size_t)N3;
    float* R0 = S + 7 * (size_t)N3;
    float* P1 = S + 8 * (size_t)N3;
    float* Rp = S + 9 * (size_t)N3;      // residual pyramid (levels 1..7)
    float* Wp = Rp + (size_t)PYR;        // correction pyramid

    // level offsets within pyramid: dims 64,32,16,8,4,2,1
    static const int off[8] = {0, 0, 262144, 294912, 299008, 299520, 299584, 299592};

    dim3 blk(128, 4, 1), grd(1, 32, 128);

    k_predictor<<<grd, blk>>>(U, V, W_, P, SG, DT, BU, BV, BW);
    k_corrector<<<grd, blk>>>(BU, BV, BW, U, V, W_, P, SG, DT, U1, V1, W1);
    k_div<<<grd, blk>>>(U1, V1, W1, DT, B);

    for (int it = 0; it < 2; ++it) {
        const float* ps = (it == 0) ? P : P1;
        k_resid<<<grd, blk>>>(ps, B, R0);

        for (int i = 1; i <= 7; ++i) {
            const float* src = (i == 1) ? R0 : (Rp + off[i - 1]);
            int md = N >> i;
            int n = md * md * md;
            int nb = (n + 255) / 256;
            k_restrict<<<nb, 256>>>(src, Rp + off[i], N >> (i - 1));
        }

        k_mglevel<<<1, 32>>>(nullptr, Rp + off[7], Wp + off[7], 1);
        for (int i = 6; i >= 1; --i) {
            int m = N >> i;
            int n = m * m * m;
            int nb = (n + 255) / 256;
            k_mglevel<<<nb, 256>>>(Wp + off[i + 1], Rp + off[i], Wp + off[i], m);
        }

        if (it == 0) {
            k_pupdate<<<grd, blk>>>(ps, Wp + off[1], R0, P1, nullptr);
        } else {
            k_copyr<<<1, 1>>>(Rp + off[7], o_r);
            k_pupdate<<<grd, blk>>>(ps, Wp + off[1], R0, o_p, o_wmg);
        }
    }

    k_final<<<grd, blk>>>(U1, V1, W1, o_p, SG, DT, o_u, o_v, o_w);
}

// round 3
// speedup vs baseline: 1.0514x; 1.0514x over previous
#include <cuda_runtime.h>

#define N   128
#define N3  (N*N*N)
#define PYR 299593

// BU BV BW U1 V1 W1 B R0 P1 (9 x N3) + pyramids
__device__ float g_scratch[9 * (size_t)N3 + 2 * (size_t)PYR];

static __device__ __forceinline__ int cl(int x) { return x < 0 ? 0 : (x > N - 1 ? N - 1 : x); }
static __device__ __forceinline__ int ix(int d, int h, int w) { return (d << 14) + (h << 7) + w; }

static __device__ __forceinline__ float4 ld4(const float* __restrict__ p, int i) {
    return *reinterpret_cast<const float4*>(p + i);
}
static __device__ __forceinline__ void st4(float* __restrict__ p, int i, float4 v) {
    *reinterpret_cast<float4*>(p + i) = v;
}
static __device__ __forceinline__ float4 operator+(float4 a, float4 b) { return make_float4(a.x+b.x, a.y+b.y, a.z+b.z, a.w+b.w); }
static __device__ __forceinline__ float4 operator-(float4 a, float4 b) { return make_float4(a.x-b.x, a.y-b.y, a.z-b.z, a.w-b.w); }
static __device__ __forceinline__ float4 operator*(float s, float4 a) { return make_float4(s*a.x, s*a.y, s*a.z, s*a.w); }
static __device__ __forceinline__ float4 operator*(float4 a, float4 b) { return make_float4(a.x*b.x, a.y*b.y, a.z*b.z, a.w*b.w); }

// 7-point stencil bundle for a float4 along w
struct S7 { float4 c, n, s, b, t; float wl, wr; };

static __device__ __forceinline__ S7 ld7(const float* __restrict__ A,
                                         int cb, int nb, int sb, int bb, int tb, int w4) {
    S7 r;
    r.c = ld4(A, cb); r.n = ld4(A, nb); r.s = ld4(A, sb); r.b = ld4(A, bb); r.t = ld4(A, tb);
    r.wl = (w4 > 0)   ? A[cb - 1] : r.c.x;
    r.wr = (w4 < 124) ? A[cb + 4] : r.c.w;
    return r;
}
static __device__ __forceinline__ float4 westv(const S7& s) { return make_float4(s.wl, s.c.x, s.c.y, s.c.z); }
static __device__ __forceinline__ float4 eastv(const S7& s) { return make_float4(s.c.y, s.c.z, s.c.w, s.wr); }

static __device__ __forceinline__ float4 rcp4(float dt, float4 g) {
    return make_float4(1.f/(1.f+dt*g.x), 1.f/(1.f+dt*g.y), 1.f/(1.f+dt*g.z), 1.f/(1.f+dt*g.w));
}
static __device__ __forceinline__ void scale7(S7& u, const S7& f) {
    u.c = u.c * f.c; u.n = u.n * f.n; u.s = u.s * f.s; u.b = u.b * f.b; u.t = u.t * f.t;
    u.wl *= f.wl; u.wr *= f.wr;
}

#define VIDX                                        \
    const int w4 = threadIdx.x << 2;                \
    const int h  = (blockIdx.y << 3) + threadIdx.y; \
    const int hS = cl(h - 1), hN = cl(h + 1);

#define VIDXD(dd)                                   \
    const int d = (dd);                             \
    const int dB = cl(d - 1), dT = cl(d + 1);       \
    const int cb = ix(d, h, w4);                    \
    const int nb = ix(d, hN, w4), sb = ix(d, hS, w4); \
    const int bb = ix(dB, h, w4), tb = ix(dT, h, w4);

// ---------------------------------------------------------------------------
__global__ void __launch_bounds__(256) k_predictor(
    const float* __restrict__ U, const float* __restrict__ V, const float* __restrict__ W_,
    const float* __restrict__ P, const float* __restrict__ SG, const float* __restrict__ DT,
    float* __restrict__ BU, float* __restrict__ BV, float* __restrict__ BW)
{
    VIDX; VIDXD(blockIdx.z);
    const float dt = DT[0];

    S7 g = ld7(SG, cb, nb, sb, bb, tb, w4);
    S7 f;
    f.c = rcp4(dt, g.c); f.n = rcp4(dt, g.n); f.s = rcp4(dt, g.s);
    f.b = rcp4(dt, g.b); f.t = rcp4(dt, g.t);
    f.wl = 1.f/(1.f+dt*g.wl); f.wr = 1.f/(1.f+dt*g.wr);

    S7 p = ld7(P, cb, nb, sb, bb, tb, w4);
    float4 gpx = 0.5f * (eastv(p) - westv(p));
    float4 gpy = 0.5f * (p.n - p.s);
    float4 gpz = 0.5f * (p.t - p.b);

    float4 uc, vc, wc;
    {
        S7 su = ld7(U, cb, nb, sb, bb, tb, w4); scale7(su, f);
        uc = su.c;
        vc = ld4(V, cb)  * f.c;
        wc = ld4(W_, cb) * f.c;
        float4 west = westv(su); if (w4 == 0) west.x = 1.0f;
        float4 east = eastv(su);
        float4 lap = west + east + su.n + su.s + su.b + su.t - 6.f * su.c;
        float4 ax = 0.5f * (east - west), ay = 0.5f * (su.n - su.s), az = 0.5f * (su.t - su.b);
        st4(BU, cb, (uc + 0.5f*dt*(lap - uc*ax - vc*ay - wc*az) - dt*gpx) * f.c);
    }
    {
        S7 sv = ld7(V, cb, nb, sb, bb, tb, w4); scale7(sv, f);
        float4 west = westv(sv), east = eastv(sv);
        float4 lap = west + east + sv.n + sv.s + sv.b + sv.t - 6.f * sv.c;
        float4 ax = 0.5f * (east - west), ay = 0.5f * (sv.n - sv.s), az = 0.5f * (sv.t - sv.b);
        st4(BV, cb, (vc + 0.5f*dt*(lap - uc*ax - vc*ay - wc*az) - dt*gpy) * f.c);
    }
    {
        S7 sw = ld7(W_, cb, nb, sb, bb, tb, w4); scale7(sw, f);
        float4 west = westv(sw), east = eastv(sw);
        float4 lap = west + east + sw.n + sw.s + sw.b + sw.t - 6.f * sw.c;
        float4 ax = 0.5f * (east - west), ay = 0.5f * (sw.n - sw.s), az = 0.5f * (sw.t - sw.b);
        st4(BW, cb, (wc + 0.5f*dt*(lap - uc*ax - vc*ay - wc*az) - dt*gpz) * f.c);
    }
}

// ---------------------------------------------------------------------------
__global__ void __launch_bounds__(256) k_corrector(
    const float* __restrict__ BU, const float* __restrict__ BV, const float* __restrict__ BW,
    const float* __restrict__ U, const float* __restrict__ V, const float* __restrict__ W_,
    const float* __restrict__ P, const float* __restrict__ SG, const float* __restrict__ DT,
    float* __restrict__ U1, float* __restrict__ V1, float* __restrict__ W1)
{
    VIDX; VIDXD(blockIdx.z);
    const float dt = DT[0];

    const float4 fc = rcp4(dt, ld4(SG, cb));
    const float4 uc = ld4(U, cb) * fc, vc = ld4(V, cb) * fc, wc = ld4(W_, cb) * fc;
    const float4 buc = ld4(BU, cb), bvc = ld4(BV, cb), bwc = ld4(BW, cb);

    S7 p = ld7(P, cb, nb, sb, bb, tb, w4);
    float4 gpx = 0.5f * (eastv(p) - westv(p));
    float4 gpy = 0.5f * (p.n - p.s);
    float4 gpz = 0.5f * (p.t - p.b);

    {
        S7 a = ld7(BU, cb, nb, sb, bb, tb, w4);
        float4 west = westv(a); if (w4 == 0) west.x = 1.0f;
        float4 east = eastv(a);
        float4 lap = west + east + a.n + a.s + a.b + a.t - 6.f * a.c;
        float4 ax = 0.5f * (east - west), ay = 0.5f * (a.n - a.s), az = 0.5f * (a.t - a.b);
        st4(U1, cb, (uc + dt*(lap - buc*ax - bvc*ay - bwc*az) - dt*gpx) * fc);
    }
    {
        S7 a = ld7(BV, cb, nb, sb, bb, tb, w4);
        float4 west = westv(a), east = eastv(a);
        float4 lap = west + east + a.n + a.s + a.b + a.t - 6.f * a.c;
        float4 ax = 0.5f * (east - west), ay = 0.5f * (a.n - a.s), az = 0.5f * (a.t - a.b);
        st4(V1, cb, (vc + dt*(lap - buc*ax - bvc*ay - bwc*az) - dt*gpy) * fc);
    }
    {
        S7 a = ld7(BW, cb, nb, sb, bb, tb, w4);
        float4 west = westv(a), east = eastv(a);
        float4 lap = west + east + a.n + a.s + a.b + a.t - 6.f * a.c;
        float4 ax = 0.5f * (east - west), ay = 0.5f * (a.n - a.s), az = 0.5f * (a.t - a.b);
        st4(W1, cb, (wc + dt*(lap - buc*ax - bvc*ay - bwc*az) - dt*gpz) * fc);
    }
}

// ---------------------------------------------------------------------------
__global__ void __launch_bounds__(256) k_div(
    const float* __restrict__ U1, const float* __restrict__ V1, const float* __restrict__ W1,
    const float* __restrict__ DT, float* __restrict__ B)
{
    VIDX; VIDXD(blockIdx.z);
    const float dt = DT[0];
    float4 u = ld4(U1, cb);
    float uwl = (w4 > 0) ? U1[cb - 1] : u.x;
    if (w4 == 0) uwl = 1.0f;
    float uwr = (w4 < 124) ? U1[cb + 4] : u.w;
    float4 west = make_float4(uwl, u.x, u.y, u.z);
    float4 east = make_float4(u.y, u.z, u.w, uwr);
    float4 vn = ld4(V1, nb), vs = ld4(V1, sb);
    float4 wt = ld4(W1, tb), wb = ld4(W1, bb);
    float r = -1.f / dt;
    st4(B, cb, r * (0.5f*(east - west) + 0.5f*(vn - vs) + 0.5f*(wt - wb)));
}

// ---------------------------------------------------------------------------
// r0 = A(edge_pad(p)) - b, fused with 128->64 restriction into Rp1
__global__ void __launch_bounds__(256) k_resid(
    const float* __restrict__ P, const float* __restrict__ B,
    float* __restrict__ R0, float* __restrict__ Rp1)
{
    __shared__ float sred[8][64];
    VIDX;
    float acc0 = 0.f, acc1 = 0.f;
    #pragma unroll
    for (int d2 = 0; d2 < 2; ++d2) {
        VIDXD((blockIdx.z << 1) + d2);
        S7 p = ld7(P, cb, nb, sb, bb, tb, w4);
        float4 west = westv(p), east = eastv(p);
        float4 lap = west + east + p.n + p.s + p.b + p.t - 6.f * p.c;
        float4 rr = lap - ld4(B, cb);
        st4(R0, cb, rr);
        acc0 += rr.x + rr.y;
        acc1 += rr.z + rr.w;
    }
    sred[threadIdx.y][threadIdx.x * 2]     = acc0;
    sred[threadIdx.y][threadIdx.x * 2 + 1] = acc1;
    __syncthreads();
    int tid = threadIdx.y * 32 + threadIdx.x;   // 0..255
    int cw = tid & 63, chh = tid >> 6;          // 64 x 4 coarse outputs
    float v = sred[2 * chh][cw] + sred[2 * chh + 1][cw];
    int dc = blockIdx.z, hc = (blockIdx.y << 2) + chh;
    Rp1[(dc * 64 + hc) * 64 + cw] = 0.125f * v;
}

// generic stride-2 restriction (used 64->32, 32->16)
__global__ void k_restrict(const float* __restrict__ src, float* __restrict__ dst, int ms)
{
    const int md = ms >> 1;
    const int n = md * md * md;
    const int t = blockIdx.x * blockDim.x + threadIdx.x;
    if (t >= n) return;
    const int w = t % md, h = (t / md) % md, d = t / (md * md);
    const int b0 = ((2 * d) * ms + 2 * h) * ms + 2 * w;
    const int ms2 = ms * ms;
    float s = src[b0] + src[b0 + 1] + src[b0 + ms] + src[b0 + ms + 1]
            + src[b0 + ms2] + src[b0 + ms2 + 1] + src[b0 + ms2 + ms] + src[b0 + ms2 + ms + 1];
    dst[t] = 0.125f * s;
}

static __device__ __forceinline__ float mgcell(const float* __restrict__ Wp, int mc,
                                               float r, int d, int h, int w, int m)
{
    auto g = [&](int dd, int hh, int ww) -> float {
        if (dd < 0 || dd >= m || hh < 0 || hh >= m || ww < 0 || ww >= m) return 0.f;
        return Wp[((dd >> 1) * mc + (hh >> 1)) * mc + (ww >> 1)];
    };
    float wc = g(d, h, w);
    float lap = g(d-1,h,w) + g(d+1,h,w) + g(d,h-1,w) + g(d,h+1,w) + g(d,h,w-1) + g(d,h,w+1) - 6.f * wc;
    return wc - lap / (-6.f) + r / (-6.f);
}

// MG level for m=32 / m=64
__global__ void k_mglevel(const float* __restrict__ cprev, const float* __restrict__ r,
                          float* __restrict__ out, int m)
{
    const int n = m * m * m;
    const int t = blockIdx.x * blockDim.x + threadIdx.x;
    if (t >= n) return;
    const int w = t % m, h = (t / m) % m, d = t / (m * m);
    out[t] = mgcell(cprev, m >> 1, r[t], d, h, w, m);
}

// ---------------------------------------------------------------------------
// Fused coarse pyramid: restrict 16->8->4->2->1, solve 1->2->4->8->16.
// Optionally writes the size-1 residual (the returned `r`).
__global__ void k_coarse(const float* __restrict__ r16g, float* __restrict__ w16g,
                         float* __restrict__ o_r)
{
    __shared__ float R16[4096], R8[512], R4[64], R2[8];
    __shared__ float W8[512], W4[64], W2[8], W1a[1], R1a[1];
    const int tid = threadIdx.x;    // 512 threads

    for (int k = tid; k < 4096; k += 512) R16[k] = r16g[k];
    __syncthreads();
    {   // 16 -> 8
        int w = tid & 7, h = (tid >> 3) & 7, d = tid >> 6;
        int b0 = ((2 * d) * 16 + 2 * h) * 16 + 2 * w;
        R8[tid] = 0.125f * (R16[b0] + R16[b0+1] + R16[b0+16] + R16[b0+17]
                          + R16[b0+256] + R16[b0+257] + R16[b0+272] + R16[b0+273]);
    }
    __syncthreads();
    if (tid < 64) {   // 8 -> 4
        int w = tid & 3, h = (tid >> 2) & 3, d = tid >> 4;
        int b0 = ((2 * d) * 8 + 2 * h) * 8 + 2 * w;
        R4[tid] = 0.125f * (R8[b0] + R8[b0+1] + R8[b0+8] + R8[b0+9]
                          + R8[b0+64] + R8[b0+65] + R8[b0+72] + R8[b0+73]);
    }
    __syncthreads();
    if (tid < 8) {    // 4 -> 2
        int w = tid & 1, h = (tid >> 1) & 1, d = tid >> 2;
        int b0 = ((2 * d) * 4 + 2 * h) * 4 + 2 * w;
        R2[tid] = 0.125f * (R4[b0] + R4[b0+1] + R4[b0+4] + R4[b0+5]
                          + R4[b0+16] + R4[b0+17] + R4[b0+20] + R4[b0+21]);
    }
    __syncthreads();
    if (tid == 0) {   // 2 -> 1, coarsest solve
        float r1 = 0.125f * (R2[0]+R2[1]+R2[2]+R2[3]+R2[4]+R2[5]+R2[6]+R2[7]);
        R1a[0] = r1;
        W1a[0] = r1 / (-6.f);
        if (o_r) o_r[0] = r1;
    }
    __syncthreads();
    if (tid < 8) {    // m = 2
        int w = tid & 1, h = (tid >> 1) & 1, d = tid >> 2;
        W2[tid] = mgcell(W1a, 1, R2[tid], d, h, w, 2);
    }
    __syncthreads();
    if (tid < 64) {   // m = 4
        int w = tid & 3, h = (tid >> 2) & 3, d = tid >> 4;
        W4[tid] = mgcell(W2, 2, R4[tid], d, h, w, 4);
    }
    __syncthreads();
    {                 // m = 8
        int w = tid & 7, h = (tid >> 3) & 7, d = tid >> 6;
        W8[tid] = mgcell(W4, 4, R8[tid], d, h, w, 8);
    }
    __syncthreads();
    for (int k = tid; k < 4096; k += 512) {   // m = 16 -> global
        int w = k & 15, h = (k >> 4) & 15, d = k >> 8;
        w16g[k] = mgcell(W8, 8, R16[k], d, h, w, 16);
    }
}

// ---------------------------------------------------------------------------
__global__ void __launch_bounds__(256) k_pupdate(
    const float* __restrict__ pold, const float* __restrict__ c1, const float* __restrict__ r0,
    float* __restrict__ pnew, float* __restrict__ wmg_out)
{
    VIDX; VIDXD(blockIdx.z);
    (void)nb; (void)sb; (void)bb; (void)tb;
    const int crow = ((d >> 1) * 64 + (h >> 1)) * 64 + (w4 >> 1);
    const float a = c1[crow], b2 = c1[crow + 1];
    const float4 wv = make_float4(a, a, b2, b2);
    const float4 r4 = ld4(r0, cb);
    const float4 pn = ld4(pold, cb) - wv - make_float4(r4.x/(-6.f), r4.y/(-6.f), r4.z/(-6.f), r4.w/(-6.f));
    st4(pnew, cb, pn);
    if (wmg_out) st4(wmg_out, cb, wv);
}

// ---------------------------------------------------------------------------
__global__ void __launch_bounds__(256) k_final(
    const float* __restrict__ U1, const float* __restrict__ V1, const float* __restrict__ W1,
    const float* __restrict__ Pf, const float* __restrict__ SG, const float* __restrict__ DT,
    float* __restrict__ OU, float* __restrict__ OV, float* __restrict__ OW)
{
    VIDX; VIDXD(blockIdx.z);
    const float dt = DT[0];
    const float4 fc = rcp4(dt, ld4(SG, cb));
    S7 p = ld7(Pf, cb, nb, sb, bb, tb, w4);
    float4 gpx = 0.5f * (eastv(p) - westv(p));
    float4 gpy = 0.5f * (p.n - p.s);
    float4 gpz = 0.5f * (p.t - p.b);
    st4(OU, cb, (ld4(U1, cb) - dt * gpx) * fc);
    st4(OV, cb, (ld4(V1, cb) - dt * gpy) * fc);
    st4(OW, cb, (ld4(W1, cb) - dt * gpz) * fc);
}

// ---------------------------------------------------------------------------
extern "C" void kernel_launch(void* const* d_in, const int* in_sizes, int n_in,
                              void* d_out, int out_size)
{
    const float* U  = (const float*)d_in[0];
    const float* V  = (const float*)d_in[1];
    const float* W_ = (const float*)d_in[2];
    const float* P  = (const float*)d_in[3];
    const float* SG = (const float*)d_in[4];
    const float* DT = (const float*)d_in[5];

    float* out   = (float*)d_out;
    float* o_u   = out;
    float* o_v   = out + (size_t)N3;
    float* o_w   = out + 2 * (size_t)N3;
    float* o_p   = out + 3 * (size_t)N3;
    float* o_wmg = out + 4 * (size_t)N3;
    float* o_r   = out + 5 * (size_t)N3;

    float* S = nullptr;
    cudaGetSymbolAddress((void**)&S, g_scratch);
    float* BU = S;
    float* BV = S + (size_t)N3;
    float* BW = S + 2 * (size_t)N3;
    float* U1 = S + 3 * (size_t)N3;
    float* V1 = S + 4 * (size_t)N3;
    float* W1 = S + 5 * (size_t)N3;
    float* B  = S + 6 * (size_t)N3;
    float* R0 = S + 7 * (size_t)N3;
    float* P1 = S + 8 * (size_t)N3;
    float* Rp1 = S + 9 * (size_t)N3;      // 64^3
    float* Rp2 = Rp1 + 262144;            // 32^3
    float* Rp3 = Rp2 + 32768;             // 16^3
    float* Wp1 = Rp3 + 4096;              // 64^3
    float* Wp2 = Wp1 + 262144;            // 32^3
    float* Wp3 = Wp2 + 32768;             // 16^3

    dim3 blk(32, 8, 1);
    dim3 grd(1, 16, 128);
    dim3 grdR(1, 16, 64);

    k_predictor<<<grd, blk>>>(U, V, W_, P, SG, DT, BU, BV, BW);
    k_corrector<<<grd, blk>>>(BU, BV, BW, U, V, W_, P, SG, DT, U1, V1, W1);
    k_div<<<grd, blk>>>(U1, V1, W1, DT, B);

    for (int it = 0; it < 2; ++it) {
        const float* ps = (it == 0) ? P : P1;
        k_resid<<<grdR, blk>>>(ps, B, R0, Rp1);
        k_restrict<<<128, 256>>>(Rp1, Rp2, 64);
        k_restrict<<<16, 256>>>(Rp2, Rp3, 32);
        k_coarse<<<1, 512>>>(Rp3, Wp3, (it == 1) ? o_r : nullptr);
        k_mglevel<<<128, 256>>>(Wp3, Rp2, Wp2, 32);
        k_mglevel<<<1024, 256>>>(Wp2, Rp1, Wp1, 64);
        if (it == 0) {
            k_pupdate<<<grd, blk>>>(ps, Wp1, R0, P1, nullptr);
        } else {
            k_pupdate<<<grd, blk>>>(ps, Wp1, R0, o_p, o_wmg);
        }
    }

    k_final<<<grd, blk>>>(U1, V1, W1, o_p, SG, DT, o_u, o_v, o_w);
}

// round 5
// speedup vs baseline: 1.4942x; 1.4212x over previous
#include <cuda_runtime.h>

#define N   128
#define N3  (N*N*N)

// BU BV BW U1 V1 W1 B R0 P1 (9 x N3) + Rp1(64^3) + Rp2(32^3) + Wp2(32^3)
__device__ float g_scratch[9 * (size_t)N3 + 262144 + 2 * 32768];

static __device__ __forceinline__ int cl(int x) { return x < 0 ? 0 : (x > N - 1 ? N - 1 : x); }
static __device__ __forceinline__ int ix(int d, int h, int w) { return (d << 14) + (h << 7) + w; }

static __device__ __forceinline__ float4 ld4(const float* __restrict__ p, int i) {
    return *reinterpret_cast<const float4*>(p + i);
}
static __device__ __forceinline__ void st4(float* __restrict__ p, int i, float4 v) {
    *reinterpret_cast<float4*>(p + i) = v;
}
static __device__ __forceinline__ float4 operator+(float4 a, float4 b) { return make_float4(a.x+b.x, a.y+b.y, a.z+b.z, a.w+b.w); }
static __device__ __forceinline__ float4 operator-(float4 a, float4 b) { return make_float4(a.x-b.x, a.y-b.y, a.z-b.z, a.w-b.w); }
static __device__ __forceinline__ float4 operator*(float s, float4 a) { return make_float4(s*a.x, s*a.y, s*a.z, s*a.w); }
static __device__ __forceinline__ float4 operator*(float4 a, float4 b) { return make_float4(a.x*b.x, a.y*b.y, a.z*b.z, a.w*b.w); }

struct S7 { float4 c, n, s, b, t; float wl, wr; };

static __device__ __forceinline__ S7 ld7(const float* __restrict__ A,
                                         int cb, int nb, int sb, int bb, int tb, int w4) {
    S7 r;
    r.c = ld4(A, cb); r.n = ld4(A, nb); r.s = ld4(A, sb); r.b = ld4(A, bb); r.t = ld4(A, tb);
    r.wl = (w4 > 0)   ? A[cb - 1] : r.c.x;
    r.wr = (w4 < 124) ? A[cb + 4] : r.c.w;
    return r;
}
static __device__ __forceinline__ float4 westv(const S7& s) { return make_float4(s.wl, s.c.x, s.c.y, s.c.z); }
static __device__ __forceinline__ float4 eastv(const S7& s) { return make_float4(s.c.y, s.c.z, s.c.w, s.wr); }

static __device__ __forceinline__ float4 rcp4(float dt, float4 g) {
    return make_float4(1.f/(1.f+dt*g.x), 1.f/(1.f+dt*g.y), 1.f/(1.f+dt*g.z), 1.f/(1.f+dt*g.w));
}
static __device__ __forceinline__ void scale7(S7& u, const S7& f) {
    u.c = u.c * f.c; u.n = u.n * f.n; u.s = u.s * f.s; u.b = u.b * f.b; u.t = u.t * f.t;
    u.wl *= f.wl; u.wr *= f.wr;
}

#define IDX6(dd)                                      \
    const int d = (dd);                               \
    const int dB = cl(d - 1), dT = cl(d + 1);         \
    const int cb = ix(d, h, w4);                      \
    const int nb = ix(d, hN, w4), sb = ix(d, hS, w4); \
    const int bb = ix(dB, h, w4), tb = ix(dT, h, w4);

// ---------------------------------------------------------------------------
// Predictor: ALL loads batched up front for max MLP. blockDim (32,4).
// ---------------------------------------------------------------------------
__global__ void __launch_bounds__(128) k_predictor(
    const float* __restrict__ U, const float* __restrict__ V, const float* __restrict__ W_,
    const float* __restrict__ P, const float* __restrict__ SG, const float* __restrict__ DT,
    float* __restrict__ BU, float* __restrict__ BV, float* __restrict__ BW)
{
    const int w4 = threadIdx.x << 2;
    const int h  = (blockIdx.y << 2) + threadIdx.y;
    const int hS = cl(h - 1), hN = cl(h + 1);
    IDX6(blockIdx.z);

    // ---- load phase (27 LDGs, all independent) ----
    S7 g  = ld7(SG, cb, nb, sb, bb, tb, w4);
    S7 p  = ld7(P,  cb, nb, sb, bb, tb, w4);
    S7 su = ld7(U,  cb, nb, sb, bb, tb, w4);
    S7 sv = ld7(V,  cb, nb, sb, bb, tb, w4);
    S7 sw = ld7(W_, cb, nb, sb, bb, tb, w4);
    const float dt = DT[0];

    // ---- compute phase ----
    S7 f;
    f.c = rcp4(dt, g.c); f.n = rcp4(dt, g.n); f.s = rcp4(dt, g.s);
    f.b = rcp4(dt, g.b); f.t = rcp4(dt, g.t);
    f.wl = 1.f/(1.f+dt*g.wl); f.wr = 1.f/(1.f+dt*g.wr);

    scale7(su, f); scale7(sv, f); scale7(sw, f);
    const float4 uc = su.c, vc = sv.c, wc = sw.c;

    float4 gpx = 0.5f * (eastv(p) - westv(p));
    float4 gpy = 0.5f * (p.n - p.s);
    float4 gpz = 0.5f * (p.t - p.b);

    {
        float4 west = westv(su); if (w4 == 0) west.x = 1.0f;
        float4 east = eastv(su);
        float4 lap = west + east + su.n + su.s + su.b + su.t - 6.f * su.c;
        float4 ax = 0.5f * (east - west), ay = 0.5f * (su.n - su.s), az = 0.5f * (su.t - su.b);
        st4(BU, cb, (uc + 0.5f*dt*(lap - uc*ax - vc*ay - wc*az) - dt*gpx) * f.c);
    }
    {
        float4 west = westv(sv), east = eastv(sv);
        float4 lap = west + east + sv.n + sv.s + sv.b + sv.t - 6.f * sv.c;
        float4 ax = 0.5f * (east - west), ay = 0.5f * (sv.n - sv.s), az = 0.5f * (sv.t - sv.b);
        st4(BV, cb, (vc + 0.5f*dt*(lap - uc*ax - vc*ay - wc*az) - dt*gpy) * f.c);
    }
    {
        float4 west = westv(sw), east = eastv(sw);
        float4 lap = west + east + sw.n + sw.s + sw.b + sw.t - 6.f * sw.c;
        float4 ax = 0.5f * (east - west), ay = 0.5f * (sw.n - sw.s), az = 0.5f * (sw.t - sw.b);
        st4(BW, cb, (wc + 0.5f*dt*(lap - uc*ax - vc*ay - wc*az) - dt*gpz) * f.c);
    }
}

// ---------------------------------------------------------------------------
__global__ void __launch_bounds__(128) k_corrector(
    const float* __restrict__ BU, const float* __restrict__ BV, const float* __restrict__ BW,
    const float* __restrict__ U, const float* __restrict__ V, const float* __restrict__ W_,
    const float* __restrict__ P, const float* __restrict__ SG, const float* __restrict__ DT,
    float* __restrict__ U1, float* __restrict__ V1, float* __restrict__ W1)
{
    const int w4 = threadIdx.x << 2;
    const int h  = (blockIdx.y << 2) + threadIdx.y;
    const int hS = cl(h - 1), hN = cl(h + 1);
    IDX6(blockIdx.z);

    // ---- load phase ----
    const float4 sg = ld4(SG, cb);
    const float4 Uc = ld4(U, cb), Vc = ld4(V, cb), Wc = ld4(W_, cb);
    S7 p = ld7(P,  cb, nb, sb, bb, tb, w4);
    S7 a = ld7(BU, cb, nb, sb, bb, tb, w4);
    S7 b = ld7(BV, cb, nb, sb, bb, tb, w4);
    S7 c = ld7(BW, cb, nb, sb, bb, tb, w4);
    const float dt = DT[0];

    // ---- compute ----
    const float4 fc = rcp4(dt, sg);
    const float4 uc = Uc * fc, vc = Vc * fc, wc = Wc * fc;
    const float4 buc = a.c, bvc = b.c, bwc = c.c;

    float4 gpx = 0.5f * (eastv(p) - westv(p));
    float4 gpy = 0.5f * (p.n - p.s);
    float4 gpz = 0.5f * (p.t - p.b);

    {
        float4 west = westv(a); if (w4 == 0) west.x = 1.0f;
        float4 east = eastv(a);
        float4 lap = west + east + a.n + a.s + a.b + a.t - 6.f * a.c;
        float4 ax = 0.5f * (east - west), ay = 0.5f * (a.n - a.s), az = 0.5f * (a.t - a.b);
        st4(U1, cb, (uc + dt*(lap - buc*ax - bvc*ay - bwc*az) - dt*gpx) * fc);
    }
    {
        float4 west = westv(b), east = eastv(b);
        float4 lap = west + east + b.n + b.s + b.b + b.t - 6.f * b.c;
        float4 ax = 0.5f * (east - west), ay = 0.5f * (b.n - b.s), az = 0.5f * (b.t - b.b);
        st4(V1, cb, (vc + dt*(lap - buc*ax - bvc*ay - bwc*az) - dt*gpy) * fc);
    }
    {
        float4 west = westv(c), east = eastv(c);
        float4 lap = west + east + c.n + c.s + c.b + c.t - 6.f * c.c;
        float4 ax = 0.5f * (east - west), ay = 0.5f * (c.n - c.s), az = 0.5f * (c.t - c.b);
        st4(W1, cb, (wc + dt*(lap - buc*ax - bvc*ay - bwc*az) - dt*gpz) * fc);
    }
}

// ---------------------------------------------------------------------------
// Iter-0 fused: b = -div(vel)/dt (stored), r0 = lap(p) - b (stored),
// plus 128->64 restriction of r0 into Rp1. 2 d-planes per block; (32,8).
// ---------------------------------------------------------------------------
__global__ void __launch_bounds__(256) k_residdiv(
    const float* __restrict__ P, const float* __restrict__ U1,
    const float* __restrict__ V1, const float* __restrict__ W1,
    const float* __restrict__ DT,
    float* __restrict__ B, float* __restrict__ R0, float* __restrict__ Rp1)
{
    __shared__ float sred[8][64];
    const int w4 = threadIdx.x << 2;
    const int h  = (blockIdx.y << 3) + threadIdx.y;
    const int hS = cl(h - 1), hN = cl(h + 1);

    S7 pp[2]; float4 u1c[2], vn[2], vs[2], wb[2], wt[2];
    float uwl[2], uwr[2]; int cbs[2];

    #pragma unroll
    for (int d2 = 0; d2 < 2; ++d2) {   // load phase: 24 LDGs
        IDX6((blockIdx.z << 1) + d2);
        cbs[d2] = cb;
        pp[d2]  = ld7(P, cb, nb, sb, bb, tb, w4);
        u1c[d2] = ld4(U1, cb);
        uwl[d2] = (w4 > 0)   ? U1[cb - 1] : u1c[d2].x;
        uwr[d2] = (w4 < 124) ? U1[cb + 4] : u1c[d2].w;
        vn[d2] = ld4(V1, nb); vs[d2] = ld4(V1, sb);
        wt[d2] = ld4(W1, tb); wb[d2] = ld4(W1, bb);
    }
    const float dt = DT[0];
    const float rdt = -1.f / dt;

    float acc0 = 0.f, acc1 = 0.f;
    #pragma unroll
    for (int d2 = 0; d2 < 2; ++d2) {
        float wl = uwl[d2]; if (w4 == 0) wl = 1.0f;
        float4 west = make_float4(wl, u1c[d2].x, u1c[d2].y, u1c[d2].z);
        float4 east = make_float4(u1c[d2].y, u1c[d2].z, u1c[d2].w, uwr[d2]);
        float4 b4 = rdt * (0.5f*(east - west) + 0.5f*(vn[d2] - vs[d2]) + 0.5f*(wt[d2] - wb[d2]));
        st4(B, cbs[d2], b4);

        float4 pw = westv(pp[d2]), pe = eastv(pp[d2]);
        float4 lap = pw + pe + pp[d2].n + pp[d2].s + pp[d2].b + pp[d2].t - 6.f * pp[d2].c;
        float4 rr = lap - b4;
        st4(R0, cbs[d2], rr);
        acc0 += rr.x + rr.y;
        acc1 += rr.z + rr.w;
    }
    sred[threadIdx.y][threadIdx.x * 2]     = acc0;
    sred[threadIdx.y][threadIdx.x * 2 + 1] = acc1;
    __syncthreads();
    int tid = threadIdx.y * 32 + threadIdx.x;
    int cw = tid & 63, chh = tid >> 6;
    float v = sred[2 * chh][cw] + sred[2 * chh + 1][cw];
    int dc = blockIdx.z, hc = (blockIdx.y << 2) + chh;
    Rp1[(dc * 64 + hc) * 64 + cw] = 0.125f * v;
}

// Iter-1 residual: r0 = lap(p) - B (B precomputed). Same fused restriction.
__global__ void __launch_bounds__(256) k_resid(
    const float* __restrict__ P, const float* __restrict__ B,
    float* __restrict__ R0, float* __restrict__ Rp1)
{
    __shared__ float sred[8][64];
    const int w4 = threadIdx.x << 2;
    const int h  = (blockIdx.y << 3) + threadIdx.y;
    const int hS = cl(h - 1), hN = cl(h + 1);

    S7 pp[2]; float4 bc[2]; int cbs[2];
    #pragma unroll
    for (int d2 = 0; d2 < 2; ++d2) {
        IDX6((blockIdx.z << 1) + d2);
        cbs[d2] = cb;
        pp[d2] = ld7(P, cb, nb, sb, bb, tb, w4);
        bc[d2] = ld4(B, cb);
    }
    float acc0 = 0.f, acc1 = 0.f;
    #pragma unroll
    for (int d2 = 0; d2 < 2; ++d2) {
        float4 pw = westv(pp[d2]), pe = eastv(pp[d2]);
        float4 lap = pw + pe + pp[d2].n + pp[d2].s + pp[d2].b + pp[d2].t - 6.f * pp[d2].c;
        float4 rr = lap - bc[d2];
        st4(R0, cbs[d2], rr);
        acc0 += rr.x + rr.y;
        acc1 += rr.z + rr.w;
    }
    sred[threadIdx.y][threadIdx.x * 2]     = acc0;
    sred[threadIdx.y][threadIdx.x * 2 + 1] = acc1;
    __syncthreads();
    int tid = threadIdx.y * 32 + threadIdx.x;
    int cw = tid & 63, chh = tid >> 6;
    float v = sred[2 * chh][cw] + sred[2 * chh + 1][cw];
    int dc = blockIdx.z, hc = (blockIdx.y << 2) + chh;
    Rp1[(dc * 64 + hc) * 64 + cw] = 0.125f * v;
}

// 64^3 -> 32^3 restriction, float4 reads / float2 writes
__global__ void __launch_bounds__(256) k_restrict64(
    const float* __restrict__ src, float* __restrict__ dst)
{
    const int t = blockIdx.x * 256 + threadIdx.x;   // 16384 threads
    const int wp = t & 15, h = (t >> 4) & 31, d = t >> 9;
    const int fb = ((2 * d) * 64 + 2 * h) * 64 + (wp << 2);
    float4 a = ld4(src, fb),        b = ld4(src, fb + 64);
    float4 c = ld4(src, fb + 4096), e = ld4(src, fb + 4160);
    float o0 = 0.125f * (a.x + a.y + b.x + b.y + c.x + c.y + e.x + e.y);
    float o1 = 0.125f * (a.z + a.w + b.z + b.w + c.z + c.w + e.z + e.w);
    *reinterpret_cast<float2*>(dst + (d * 32 + h) * 32 + (wp << 1)) = make_float2(o0, o1);
}

static __device__ __forceinline__ float mgcell(const float* __restrict__ Wp, int mc,
                                               float r, int d, int h, int w, int m)
{
    auto g = [&](int dd, int hh, int ww) -> float {
        if (dd < 0 || dd >= m || hh < 0 || hh >= m || ww < 0 || ww >= m) return 0.f;
        return Wp[((dd >> 1) * mc + (hh >> 1)) * mc + (ww >> 1)];
    };
    float wc = g(d, h, w);
    float lap = g(d-1,h,w) + g(d+1,h,w) + g(d,h-1,w) + g(d,h+1,w) + g(d,h,w-1) + g(d,h,w+1) - 6.f * wc;
    return wc - lap / (-6.f) + r / (-6.f);
}

// ---------------------------------------------------------------------------
// Single-block coarse solver: restrict 32->16->8->4->2->1, solve 1->...->32.
// ---------------------------------------------------------------------------
__global__ void __launch_bounds__(1024) k_coarse32(
    const float* __restrict__ R32, float* __restrict__ W32, float* __restrict__ o_r)
{
    __shared__ float R16[4096], R8[512], R4[64], R2[8];
    __shared__ float W16s[4096], W8[512], W4[64], W2[8], W1a[1];
    const int tid = threadIdx.x;

    #pragma unroll
    for (int k = tid; k < 4096; k += 1024) {   // 32 -> 16
        int w = k & 15, h = (k >> 4) & 15, d = k >> 8;
        int b0 = ((2 * d) * 32 + 2 * h) * 32 + 2 * w;
        R16[k] = 0.125f * (R32[b0] + R32[b0+1] + R32[b0+32] + R32[b0+33]
                         + R32[b0+1024] + R32[b0+1025] + R32[b0+1056] + R32[b0+1057]);
    }
    __syncthreads();
    if (tid < 512) {   // 16 -> 8
        int w = tid & 7, h = (tid >> 3) & 7, d = tid >> 6;
        int b0 = ((2 * d) * 16 + 2 * h) * 16 + 2 * w;
        R8[tid] = 0.125f * (R16[b0] + R16[b0+1] + R16[b0+16] + R16[b0+17]
                          + R16[b0+256] + R16[b0+257] + R16[b0+272] + R16[b0+273]);
    }
    __syncthreads();
    if (tid < 64) {    // 8 -> 4
        int w = tid & 3, h = (tid >> 2) & 3, d = tid >> 4;
        int b0 = ((2 * d) * 8 + 2 * h) * 8 + 2 * w;
        R4[tid] = 0.125f * (R8[b0] + R8[b0+1] + R8[b0+8] + R8[b0+9]
                          + R8[b0+64] + R8[b0+65] + R8[b0+72] + R8[b0+73]);
    }
    __syncthreads();
    if (tid < 8) {     // 4 -> 2
        int w = tid & 1, h = (tid >> 1) & 1, d = tid >> 2;
        int b0 = ((2 * d) * 4 + 2 * h) * 4 + 2 * w;
        R2[tid] = 0.125f * (R4[b0] + R4[b0+1] + R4[b0+4] + R4[b0+5]
                          + R4[b0+16] + R4[b0+17] + R4[b0+20] + R4[b0+21]);
    }
    __syncthreads();
    if (tid == 0) {    // 2 -> 1 + coarsest solve
        float r1 = 0.125f * (R2[0]+R2[1]+R2[2]+R2[3]+R2[4]+R2[5]+R2[6]+R2[7]);
        W1a[0] = r1 / (-6.f);
        if (o_r) o_r[0] = r1;
    }
    __syncthreads();
    if (tid < 8) {
        int w = tid & 1, h = (tid >> 1) & 1, d = tid >> 2;
        W2[tid] = mgcell(W1a, 1, R2[tid], d, h, w, 2);
    }
    __syncthreads();
    if (tid < 64) {
        int w = tid & 3, h = (tid >> 2) & 3, d = tid >> 4;
        W4[tid] = mgcell(W2, 2, R4[tid], d, h, w, 4);
    }
    __syncthreads();
    if (tid < 512) {
        int w = tid & 7, h = (tid >> 3) & 7, d = tid >> 6;
        W8[tid] = mgcell(W4, 4, R8[tid], d, h, w, 8);
    }
    __syncthreads();
    #pragma unroll
    for (int k = tid; k < 4096; k += 1024) {
        int w = k & 15, h = (k >> 4) & 15, d = k >> 8;
        W16s[k] = mgcell(W8, 8, R16[k], d, h, w, 16);
    }
    __syncthreads();
    #pragma unroll
    for (int k = tid; k < 32768; k += 1024) {
        int w = k & 31, h = (k >> 5) & 31, d = k >> 10;
        W32[k] = mgcell(W16s, 16, R32[k], d, h, w, 32);
    }
}

// ---------------------------------------------------------------------------
// p-update with 64-level MG solve fused: wmg(fine) = mgcell_64(W32, Rp1)
// ---------------------------------------------------------------------------
__global__ void __launch_bounds__(256) k_pupdate(
    const float* __restrict__ pold, const float* __restrict__ W32,
    const float* __restrict__ Rp1, const float* __restrict__ r0,
    float* __restrict__ pnew, float* __restrict__ wmg_out)
{
    const int w4 = threadIdx.x << 2;
    const int h  = (blockIdx.y << 3) + threadIdx.y;
    const int d  = blockIdx.z;
    const int cb = ix(d, h, w4);

    const int d64 = d >> 1, h64 = h >> 1, cw0 = w4 >> 1;
    const int crow = (d64 * 64 + h64) * 64 + cw0;
    const float r64_0 = Rp1[crow], r64_1 = Rp1[crow + 1];
    const float4 r4 = ld4(r0, cb);
    const float4 po = ld4(pold, cb);

    const float mg0 = mgcell(W32, 32, r64_0, d64, h64, cw0,     64);
    const float mg1 = mgcell(W32, 32, r64_1, d64, h64, cw0 + 1, 64);
    const float4 wv = make_float4(mg0, mg0, mg1, mg1);
    const float4 pn = po - wv - make_float4(r4.x/(-6.f), r4.y/(-6.f), r4.z/(-6.f), r4.w/(-6.f));
    st4(pnew, cb, pn);
    if (wmg_out) st4(wmg_out, cb, wv);
}

// ---------------------------------------------------------------------------
__global__ void __launch_bounds__(256) k_final(
    const float* __restrict__ U1, const float* __restrict__ V1, const float* __restrict__ W1,
    const float* __restrict__ Pf, const float* __restrict__ SG, const float* __restrict__ DT,
    float* __restrict__ OU, float* __restrict__ OV, float* __restrict__ OW)
{
    const int w4 = threadIdx.x << 2;
    const int h  = (blockIdx.y << 3) + threadIdx.y;
    const int hS = cl(h - 1), hN = cl(h + 1);
    IDX6(blockIdx.z);

    S7 p = ld7(Pf, cb, nb, sb, bb, tb, w4);
    const float4 sg = ld4(SG, cb);
    const float4 u1 = ld4(U1, cb), v1 = ld4(V1, cb), w1 = ld4(W1, cb);
    const float dt = DT[0];

    const float4 fc = rcp4(dt, sg);
    float4 gpx = 0.5f * (eastv(p) - westv(p));
    float4 gpy = 0.5f * (p.n - p.s);
    float4 gpz = 0.5f * (p.t - p.b);
    st4(OU, cb, (u1 - dt * gpx) * fc);
    st4(OV, cb, (v1 - dt * gpy) * fc);
    st4(OW, cb, (w1 - dt * gpz) * fc);
}

// ---------------------------------------------------------------------------
extern "C" void kernel_launch(void* const* d_in, const int* in_sizes, int n_in,
                              void* d_out, int out_size)
{
    const float* U  = (const float*)d_in[0];
    const float* V  = (const float*)d_in[1];
    const float* W_ = (const float*)d_in[2];
    const float* P  = (const float*)d_in[3];
    const float* SG = (const float*)d_in[4];
    const float* DT = (const float*)d_in[5];

    float* out   = (float*)d_out;
    float* o_u   = out;
    float* o_v   = out + (size_t)N3;
    float* o_w   = out + 2 * (size_t)N3;
    float* o_p   = out + 3 * (size_t)N3;
    float* o_wmg = out + 4 * (size_t)N3;
    float* o_r   = out + 5 * (size_t)N3;

    float* S = nullptr;
    cudaGetSymbolAddress((void**)&S, g_scratch);
    float* BU = S;
    float* BV = S + (size_t)N3;
    float* BW = S + 2 * (size_t)N3;
    float* U1 = S + 3 * (size_t)N3;
    float* V1 = S + 4 * (size_t)N3;
    float* W1 = S + 5 * (size_t)N3;
    float* B  = S + 6 * (size_t)N3;
    float* R0 = S + 7 * (size_t)N3;
    float* P1 = S + 8 * (size_t)N3;
    float* Rp1 = S + 9 * (size_t)N3;     // 64^3
    float* Rp2 = Rp1 + 262144;           // 32^3
    float* Wp2 = Rp2 + 32768;            // 32^3

    dim3 blkF(32, 4), grdF(1, 32, 128);     // fat kernels, 128 thr
    dim3 blkR(32, 8), grdR(1, 16, 64);      // residual (2 planes/block)
    dim3 grdP(1, 16, 128);                  // full-depth grids with blkR

    k_predictor<<<grdF, blkF>>>(U, V, W_, P, SG, DT, BU, BV, BW);
    k_corrector<<<grdF, blkF>>>(BU, BV, BW, U, V, W_, P, SG, DT, U1, V1, W1);

    // iteration 0 (div fused into residual)
    k_residdiv<<<grdR, blkR>>>(P, U1, V1, W1, DT, B, R0, Rp1);
    k_restrict64<<<64, 256>>>(Rp1, Rp2);
    k_coarse32<<<1, 1024>>>(Rp2, Wp2, nullptr);
    k_pupdate<<<grdP, blkR>>>(P, Wp2, Rp1, R0, P1, nullptr);

    // iteration 1
    k_resid<<<grdR, blkR>>>(P1, B, R0, Rp1);
    k_restrict64<<<64, 256>>>(Rp1, Rp2);
    k_coarse32<<<1, 1024>>>(Rp2, Wp2, o_r);
    k_pupdate<<<grdP, blkR>>>(P1, Wp2, Rp1, R0, o_p, o_wmg);

    k_final<<<grdP, blkR>>>(U1, V1, W1, o_p, SG, DT, o_u, o_v, o_w);
}

// round 6
// speedup vs baseline: 1.6420x; 1.0989x over previous
#include <cuda_runtime.h>

#define N   128
#define N3  (N*N*N)

// BU BV BW U1 V1 W1 B R0 P1 (9 x N3) + Rp1(64^3) + Rp2(32^3) + W32(32^3) + Rp3(16^3) + W16(16^3)
__device__ float g_scratch[9 * (size_t)N3 + 262144 + 2 * 32768 + 2 * 4096];

static __device__ __forceinline__ int cl(int x) { return x < 0 ? 0 : (x > N - 1 ? N - 1 : x); }
static __device__ __forceinline__ int ix(int d, int h, int w) { return (d << 14) + (h << 7) + w; }

static __device__ __forceinline__ float4 ld4(const float* __restrict__ p, int i) {
    return *reinterpret_cast<const float4*>(p + i);
}
static __device__ __forceinline__ void st4(float* __restrict__ p, int i, float4 v) {
    *reinterpret_cast<float4*>(p + i) = v;
}
static __device__ __forceinline__ float4 operator+(float4 a, float4 b) { return make_float4(a.x+b.x, a.y+b.y, a.z+b.z, a.w+b.w); }
static __device__ __forceinline__ float4 operator-(float4 a, float4 b) { return make_float4(a.x-b.x, a.y-b.y, a.z-b.z, a.w-b.w); }
static __device__ __forceinline__ float4 operator*(float s, float4 a) { return make_float4(s*a.x, s*a.y, s*a.z, s*a.w); }
static __device__ __forceinline__ float4 operator*(float4 a, float4 b) { return make_float4(a.x*b.x, a.y*b.y, a.z*b.z, a.w*b.w); }

struct S7 { float4 c, n, s, b, t; float wl, wr; };

static __device__ __forceinline__ S7 ld7(const float* __restrict__ A,
                                         int cb, int nb, int sb, int bb, int tb, int w4) {
    S7 r;
    r.c = ld4(A, cb); r.n = ld4(A, nb); r.s = ld4(A, sb); r.b = ld4(A, bb); r.t = ld4(A, tb);
    r.wl = (w4 > 0)   ? A[cb - 1] : r.c.x;
    r.wr = (w4 < 124) ? A[cb + 4] : r.c.w;
    return r;
}
static __device__ __forceinline__ float4 westv(const S7& s) { return make_float4(s.wl, s.c.x, s.c.y, s.c.z); }
static __device__ __forceinline__ float4 eastv(const S7& s) { return make_float4(s.c.y, s.c.z, s.c.w, s.wr); }

static __device__ __forceinline__ float4 rcp4(float dt, float4 g) {
    return make_float4(1.f/(1.f+dt*g.x), 1.f/(1.f+dt*g.y), 1.f/(1.f+dt*g.z), 1.f/(1.f+dt*g.w));
}
static __device__ __forceinline__ void scale7(S7& u, const S7& f) {
    u.c = u.c * f.c; u.n = u.n * f.n; u.s = u.s * f.s; u.b = u.b * f.b; u.t = u.t * f.t;
    u.wl *= f.wl; u.wr *= f.wr;
}

#define IDX6(dd)                                      \
    const int d = (dd);                               \
    const int dB = cl(d - 1), dT = cl(d + 1);         \
    const int cb = ix(d, h, w4);                      \
    const int nb = ix(d, hN, w4), sb = ix(d, hS, w4); \
    const int bb = ix(dB, h, w4), tb = ix(dT, h, w4);

// ---------------------------------------------------------------------------
__global__ void __launch_bounds__(128) k_predictor(
    const float* __restrict__ U, const float* __restrict__ V, const float* __restrict__ W_,
    const float* __restrict__ P, const float* __restrict__ SG, const float* __restrict__ DT,
    float* __restrict__ BU, float* __restrict__ BV, float* __restrict__ BW)
{
    const int w4 = threadIdx.x << 2;
    const int h  = (blockIdx.y << 2) + threadIdx.y;
    const int hS = cl(h - 1), hN = cl(h + 1);
    IDX6(blockIdx.z);

    S7 g  = ld7(SG, cb, nb, sb, bb, tb, w4);
    S7 p  = ld7(P,  cb, nb, sb, bb, tb, w4);
    S7 su = ld7(U,  cb, nb, sb, bb, tb, w4);
    S7 sv = ld7(V,  cb, nb, sb, bb, tb, w4);
    S7 sw = ld7(W_, cb, nb, sb, bb, tb, w4);
    const float dt = DT[0];

    S7 f;
    f.c = rcp4(dt, g.c); f.n = rcp4(dt, g.n); f.s = rcp4(dt, g.s);
    f.b = rcp4(dt, g.b); f.t = rcp4(dt, g.t);
    f.wl = 1.f/(1.f+dt*g.wl); f.wr = 1.f/(1.f+dt*g.wr);

    scale7(su, f); scale7(sv, f); scale7(sw, f);
    const float4 uc = su.c, vc = sv.c, wc = sw.c;

    float4 gpx = 0.5f * (eastv(p) - westv(p));
    float4 gpy = 0.5f * (p.n - p.s);
    float4 gpz = 0.5f * (p.t - p.b);

    {
        float4 west = westv(su); if (w4 == 0) west.x = 1.0f;
        float4 east = eastv(su);
        float4 lap = west + east + su.n + su.s + su.b + su.t - 6.f * su.c;
        float4 ax = 0.5f * (east - west), ay = 0.5f * (su.n - su.s), az = 0.5f * (su.t - su.b);
        st4(BU, cb, (uc + 0.5f*dt*(lap - uc*ax - vc*ay - wc*az) - dt*gpx) * f.c);
    }
    {
        float4 west = westv(sv), east = eastv(sv);
        float4 lap = west + east + sv.n + sv.s + sv.b + sv.t - 6.f * sv.c;
        float4 ax = 0.5f * (east - west), ay = 0.5f * (sv.n - sv.s), az = 0.5f * (sv.t - sv.b);
        st4(BV, cb, (vc + 0.5f*dt*(lap - uc*ax - vc*ay - wc*az) - dt*gpy) * f.c);
    }
    {
        float4 west = westv(sw), east = eastv(sw);
        float4 lap = west + east + sw.n + sw.s + sw.b + sw.t - 6.f * sw.c;
        float4 ax = 0.5f * (east - west), ay = 0.5f * (sw.n - sw.s), az = 0.5f * (sw.t - sw.b);
        st4(BW, cb, (wc + 0.5f*dt*(lap - uc*ax - vc*ay - wc*az) - dt*gpz) * f.c);
    }
}

// ---------------------------------------------------------------------------
__global__ void __launch_bounds__(128) k_corrector(
    const float* __restrict__ BU, const float* __restrict__ BV, const float* __restrict__ BW,
    const float* __restrict__ U, const float* __restrict__ V, const float* __restrict__ W_,
    const float* __restrict__ P, const float* __restrict__ SG, const float* __restrict__ DT,
    float* __restrict__ U1, float* __restrict__ V1, float* __restrict__ W1)
{
    const int w4 = threadIdx.x << 2;
    const int h  = (blockIdx.y << 2) + threadIdx.y;
    const int hS = cl(h - 1), hN = cl(h + 1);
    IDX6(blockIdx.z);

    const float4 sg = ld4(SG, cb);
    const float4 Uc = ld4(U, cb), Vc = ld4(V, cb), Wc = ld4(W_, cb);
    S7 p = ld7(P,  cb, nb, sb, bb, tb, w4);
    S7 a = ld7(BU, cb, nb, sb, bb, tb, w4);
    S7 b = ld7(BV, cb, nb, sb, bb, tb, w4);
    S7 c = ld7(BW, cb, nb, sb, bb, tb, w4);
    const float dt = DT[0];

    const float4 fc = rcp4(dt, sg);
    const float4 uc = Uc * fc, vc = Vc * fc, wc = Wc * fc;
    const float4 buc = a.c, bvc = b.c, bwc = c.c;

    float4 gpx = 0.5f * (eastv(p) - westv(p));
    float4 gpy = 0.5f * (p.n - p.s);
    float4 gpz = 0.5f * (p.t - p.b);

    {
        float4 west = westv(a); if (w4 == 0) west.x = 1.0f;
        float4 east = eastv(a);
        float4 lap = west + east + a.n + a.s + a.b + a.t - 6.f * a.c;
        float4 ax = 0.5f * (east - west), ay = 0.5f * (a.n - a.s), az = 0.5f * (a.t - a.b);
        st4(U1, cb, (uc + dt*(lap - buc*ax - bvc*ay - bwc*az) - dt*gpx) * fc);
    }
    {
        float4 west = westv(b), east = eastv(b);
        float4 lap = west + east + b.n + b.s + b.b + b.t - 6.f * b.c;
        float4 ax = 0.5f * (east - west), ay = 0.5f * (b.n - b.s), az = 0.5f * (b.t - b.b);
        st4(V1, cb, (vc + dt*(lap - buc*ax - bvc*ay - bwc*az) - dt*gpy) * fc);
    }
    {
        float4 west = westv(c), east = eastv(c);
        float4 lap = west + east + c.n + c.s + c.b + c.t - 6.f * c.c;
        float4 ax = 0.5f * (east - west), ay = 0.5f * (c.n - c.s), az = 0.5f * (c.t - c.b);
        st4(W1, cb, (wc + dt*(lap - buc*ax - bvc*ay - bwc*az) - dt*gpz) * fc);
    }
}

// ---------------------------------------------------------------------------
__global__ void __launch_bounds__(256) k_residdiv(
    const float* __restrict__ P, const float* __restrict__ U1,
    const float* __restrict__ V1, const float* __restrict__ W1,
    const float* __restrict__ DT,
    float* __restrict__ B, float* __restrict__ R0, float* __restrict__ Rp1)
{
    __shared__ float sred[8][64];
    const int w4 = threadIdx.x << 2;
    const int h  = (blockIdx.y << 3) + threadIdx.y;
    const int hS = cl(h - 1), hN = cl(h + 1);

    S7 pp[2]; float4 u1c[2], vn[2], vs[2], wb[2], wt[2];
    float uwl[2], uwr[2]; int cbs[2];

    #pragma unroll
    for (int d2 = 0; d2 < 2; ++d2) {
        IDX6((blockIdx.z << 1) + d2);
        cbs[d2] = cb;
        pp[d2]  = ld7(P, cb, nb, sb, bb, tb, w4);
        u1c[d2] = ld4(U1, cb);
        uwl[d2] = (w4 > 0)   ? U1[cb - 1] : u1c[d2].x;
        uwr[d2] = (w4 < 124) ? U1[cb + 4] : u1c[d2].w;
        vn[d2] = ld4(V1, nb); vs[d2] = ld4(V1, sb);
        wt[d2] = ld4(W1, tb); wb[d2] = ld4(W1, bb);
    }
    const float dt = DT[0];
    const float rdt = -1.f / dt;

    float acc0 = 0.f, acc1 = 0.f;
    #pragma unroll
    for (int d2 = 0; d2 < 2; ++d2) {
        float wl = uwl[d2]; if (w4 == 0) wl = 1.0f;
        float4 west = make_float4(wl, u1c[d2].x, u1c[d2].y, u1c[d2].z);
        float4 east = make_float4(u1c[d2].y, u1c[d2].z, u1c[d2].w, uwr[d2]);
        float4 b4 = rdt * (0.5f*(east - west) + 0.5f*(vn[d2] - vs[d2]) + 0.5f*(wt[d2] - wb[d2]));
        st4(B, cbs[d2], b4);

        float4 pw = westv(pp[d2]), pe = eastv(pp[d2]);
        float4 lap = pw + pe + pp[d2].n + pp[d2].s + pp[d2].b + pp[d2].t - 6.f * pp[d2].c;
        float4 rr = lap - b4;
        st4(R0, cbs[d2], rr);
        acc0 += rr.x + rr.y;
        acc1 += rr.z + rr.w;
    }
    sred[threadIdx.y][threadIdx.x * 2]     = acc0;
    sred[threadIdx.y][threadIdx.x * 2 + 1] = acc1;
    __syncthreads();
    int tid = threadIdx.y * 32 + threadIdx.x;
    int cw = tid & 63, chh = tid >> 6;
    float v = sred[2 * chh][cw] + sred[2 * chh + 1][cw];
    int dc = blockIdx.z, hc = (blockIdx.y << 2) + chh;
    Rp1[(dc * 64 + hc) * 64 + cw] = 0.125f * v;
}

// ---------------------------------------------------------------------------
__global__ void __launch_bounds__(256) k_resid(
    const float* __restrict__ P, const float* __restrict__ B,
    float* __restrict__ R0, float* __restrict__ Rp1)
{
    __shared__ float sred[8][64];
    const int w4 = threadIdx.x << 2;
    const int h  = (blockIdx.y << 3) + threadIdx.y;
    const int hS = cl(h - 1), hN = cl(h + 1);

    S7 pp[2]; float4 bc[2]; int cbs[2];
    #pragma unroll
    for (int d2 = 0; d2 < 2; ++d2) {
        IDX6((blockIdx.z << 1) + d2);
        cbs[d2] = cb;
        pp[d2] = ld7(P, cb, nb, sb, bb, tb, w4);
        bc[d2] = ld4(B, cb);
    }
    float acc0 = 0.f, acc1 = 0.f;
    #pragma unroll
    for (int d2 = 0; d2 < 2; ++d2) {
        float4 pw = westv(pp[d2]), pe = eastv(pp[d2]);
        float4 lap = pw + pe + pp[d2].n + pp[d2].s + pp[d2].b + pp[d2].t - 6.f * pp[d2].c;
        float4 rr = lap - bc[d2];
        st4(R0, cbs[d2], rr);
        acc0 += rr.x + rr.y;
        acc1 += rr.z + rr.w;
    }
    sred[threadIdx.y][threadIdx.x * 2]     = acc0;
    sred[threadIdx.y][threadIdx.x * 2 + 1] = acc1;
    __syncthreads();
    int tid = threadIdx.y * 32 + threadIdx.x;
    int cw = tid & 63, chh = tid >> 6;
    float v = sred[2 * chh][cw] + sred[2 * chh + 1][cw];
    int dc = blockIdx.z, hc = (blockIdx.y << 2) + chh;
    Rp1[(dc * 64 + hc) * 64 + cw] = 0.125f * v;
}

// ---------------------------------------------------------------------------
// Two-level restriction 64^3 -> 32^3 AND 16^3, one 8^3 tile per block.
// ---------------------------------------------------------------------------
__global__ void __launch_bounds__(512) k_restrict2(
    const float* __restrict__ Rp1, float* __restrict__ Rp2, float* __restrict__ Rp3)
{
    __shared__ float s[512];
    __shared__ float s2[64];
    const int tid = threadIdx.x;
    const int bw = blockIdx.x & 7, bh = (blockIdx.x >> 3) & 7, bd = blockIdx.x >> 6;
    const int lw = tid & 7, lh = (tid >> 3) & 7, ld = tid >> 6;
    const int gd = bd * 8 + ld, gh = bh * 8 + lh, gw = bw * 8 + lw;
    s[tid] = Rp1[(gd * 64 + gh) * 64 + gw];
    __syncthreads();
    if (tid < 64) {
        int cw = tid & 3, ch = (tid >> 2) & 3, cd = tid >> 4;
        int b0 = (cd * 2) * 64 + (ch * 2) * 8 + cw * 2;
        float v = 0.125f * (s[b0] + s[b0+1] + s[b0+8] + s[b0+9]
                          + s[b0+64] + s[b0+65] + s[b0+72] + s[b0+73]);
        s2[tid] = v;
        Rp2[((bd*4+cd) * 32 + (bh*4+ch)) * 32 + (bw*4+cw)] = v;
    }
    __syncthreads();
    if (tid < 8) {
        int cw = tid & 1, ch = (tid >> 1) & 1, cd = tid >> 2;
        int b0 = (cd * 2) * 16 + (ch * 2) * 4 + cw * 2;
        float v = 0.125f * (s2[b0] + s2[b0+1] + s2[b0+4] + s2[b0+5]
                          + s2[b0+16] + s2[b0+17] + s2[b0+20] + s2[b0+21]);
        Rp3[((bd*2+cd) * 16 + (bh*2+ch)) * 16 + (bw*2+cw)] = v;
    }
}

static __device__ __forceinline__ float mgcell(const float* __restrict__ Wp, int mc,
                                               float r, int d, int h, int w, int m)
{
    auto g = [&](int dd, int hh, int ww) -> float {
        if (dd < 0 || dd >= m || hh < 0 || hh >= m || ww < 0 || ww >= m) return 0.f;
        return Wp[((dd >> 1) * mc + (hh >> 1)) * mc + (ww >> 1)];
    };
    float wc = g(d, h, w);
    float lap = g(d-1,h,w) + g(d+1,h,w) + g(d,h-1,w) + g(d,h+1,w) + g(d,h,w-1) + g(d,h,w+1) - 6.f * wc;
    return wc - lap / (-6.f) + r / (-6.f);
}

// ---------------------------------------------------------------------------
// Single-block coarse solver on 16^3 only: restrict 16->8->4->2->1, solve up to W16.
// ---------------------------------------------------------------------------
__global__ void __launch_bounds__(512) k_coarse16(
    const float* __restrict__ R16g, float* __restrict__ W16g, float* __restrict__ o_r)
{
    __shared__ float R16[4096], R8[512], R4[64], R2[8];
    __shared__ float W8[512], W4[64], W2[8], W1a[1];
    const int tid = threadIdx.x;

    #pragma unroll
    for (int k = tid; k < 4096; k += 512) R16[k] = R16g[k];
    __syncthreads();
    {   // 16 -> 8
        int w = tid & 7, h = (tid >> 3) & 7, d = tid >> 6;
        int b0 = ((2 * d) * 16 + 2 * h) * 16 + 2 * w;
        R8[tid] = 0.125f * (R16[b0] + R16[b0+1] + R16[b0+16] + R16[b0+17]
                          + R16[b0+256] + R16[b0+257] + R16[b0+272] + R16[b0+273]);
    }
    __syncthreads();
    if (tid < 64) {
        int w = tid & 3, h = (tid >> 2) & 3, d = tid >> 4;
        int b0 = ((2 * d) * 8 + 2 * h) * 8 + 2 * w;
        R4[tid] = 0.125f * (R8[b0] + R8[b0+1] + R8[b0+8] + R8[b0+9]
                          + R8[b0+64] + R8[b0+65] + R8[b0+72] + R8[b0+73]);
    }
    __syncthreads();
    if (tid < 8) {
        int w = tid & 1, h = (tid >> 1) & 1, d = tid >> 2;
        int b0 = ((2 * d) * 4 + 2 * h) * 4 + 2 * w;
        R2[tid] = 0.125f * (R4[b0] + R4[b0+1] + R4[b0+4] + R4[b0+5]
                          + R4[b0+16] + R4[b0+17] + R4[b0+20] + R4[b0+21]);
    }
    __syncthreads();
    if (tid == 0) {
        float r1 = 0.125f * (R2[0]+R2[1]+R2[2]+R2[3]+R2[4]+R2[5]+R2[6]+R2[7]);
        W1a[0] = r1 / (-6.f);
        if (o_r) o_r[0] = r1;
    }
    __syncthreads();
    if (tid < 8) {
        int w = tid & 1, h = (tid >> 1) & 1, d = tid >> 2;
        W2[tid] = mgcell(W1a, 1, R2[tid], d, h, w, 2);
    }
    __syncthreads();
    if (tid < 64) {
        int w = tid & 3, h = (tid >> 2) & 3, d = tid >> 4;
        W4[tid] = mgcell(W2, 2, R4[tid], d, h, w, 4);
    }
    __syncthreads();
    {
        int w = tid & 7, h = (tid >> 3) & 7, d = tid >> 6;
        W8[tid] = mgcell(W4, 4, R8[tid], d, h, w, 8);
    }
    __syncthreads();
    #pragma unroll
    for (int k = tid; k < 4096; k += 512) {
        int w = k & 15, h = (k >> 4) & 15, d = k >> 8;
        W16g[k] = mgcell(W8, 8, R16[k], d, h, w, 16);
    }
}

// m=32 MG level, grid-wide (W16 is tiny and L2-hot)
__global__ void __launch_bounds__(256) k_mg32(
    const float* __restrict__ W16, const float* __restrict__ Rp2, float* __restrict__ W32)
{
    const int t = blockIdx.x * 256 + threadIdx.x;   // 32768
    const int w = t & 31, h = (t >> 5) & 31, d = t >> 10;
    W32[t] = mgcell(W16, 16, Rp2[t], d, h, w, 32);
}

// ---------------------------------------------------------------------------
__global__ void __launch_bounds__(256) k_pupdate(
    const float* __restrict__ pold, const float* __restrict__ W32,
    const float* __restrict__ Rp1, const float* __restrict__ r0,
    float* __restrict__ pnew, float* __restrict__ wmg_out)
{
    const int w4 = threadIdx.x << 2;
    const int h  = (blockIdx.y << 3) + threadIdx.y;
    const int d  = blockIdx.z;
    const int cb = ix(d, h, w4);

    const int d64 = d >> 1, h64 = h >> 1, cw0 = w4 >> 1;
    const int crow = (d64 * 64 + h64) * 64 + cw0;
    const float r64_0 = Rp1[crow], r64_1 = Rp1[crow + 1];
    const float4 r4 = ld4(r0, cb);
    const float4 po = ld4(pold, cb);

    const float mg0 = mgcell(W32, 32, r64_0, d64, h64, cw0,     64);
    const float mg1 = mgcell(W32, 32, r64_1, d64, h64, cw0 + 1, 64);
    const float4 wv = make_float4(mg0, mg0, mg1, mg1);
    const float4 pn = po - wv - make_float4(r4.x/(-6.f), r4.y/(-6.f), r4.z/(-6.f), r4.w/(-6.f));
    st4(pnew, cb, pn);
    if (wmg_out) st4(wmg_out, cb, wv);
}

// ---------------------------------------------------------------------------
__global__ void __launch_bounds__(256) k_final(
    const float* __restrict__ U1, const float* __restrict__ V1, const float* __restrict__ W1,
    const float* __restrict__ Pf, const float* __restrict__ SG, const float* __restrict__ DT,
    float* __restrict__ OU, float* __restrict__ OV, float* __restrict__ OW)
{
    const int w4 = threadIdx.x << 2;
    const int h  = (blockIdx.y << 3) + threadIdx.y;
    const int hS = cl(h - 1), hN = cl(h + 1);
    IDX6(blockIdx.z);

    S7 p = ld7(Pf, cb, nb, sb, bb, tb, w4);
    const float4 sg = ld4(SG, cb);
    const float4 u1 = ld4(U1, cb), v1 = ld4(V1, cb), w1 = ld4(W1, cb);
    const float dt = DT[0];

    const float4 fc = rcp4(dt, sg);
    float4 gpx = 0.5f * (eastv(p) - westv(p));
    float4 gpy = 0.5f * (p.n - p.s);
    float4 gpz = 0.5f * (p.t - p.b);
    st4(OU, cb, (u1 - dt * gpx) * fc);
    st4(OV, cb, (v1 - dt * gpy) * fc);
    st4(OW, cb, (w1 - dt * gpz) * fc);
}

// ---------------------------------------------------------------------------
extern "C" void kernel_launch(void* const* d_in, const int* in_sizes, int n_in,
                              void* d_out, int out_size)
{
    const float* U  = (const float*)d_in[0];
    const float* V  = (const float*)d_in[1];
    const float* W_ = (const float*)d_in[2];
    const float* P  = (const float*)d_in[3];
    const float* SG = (const float*)d_in[4];
    const float* DT = (const float*)d_in[5];

    float* out   = (float*)d_out;
    float* o_u   = out;
    float* o_v   = out + (size_t)N3;
    float* o_w   = out + 2 * (size_t)N3;
    float* o_p   = out + 3 * (size_t)N3;
    float* o_wmg = out + 4 * (size_t)N3;
    float* o_r   = out + 5 * (size_t)N3;

    float* S = nullptr;
    cudaGetSymbolAddress((void**)&S, g_scratch);
    float* BU = S;
    float* BV = S + (size_t)N3;
    float* BW = S + 2 * (size_t)N3;
    float* U1 = S + 3 * (size_t)N3;
    float* V1 = S + 4 * (size_t)N3;
    float* W1 = S + 5 * (size_t)N3;
    float* B  = S + 6 * (size_t)N3;
    float* R0 = S + 7 * (size_t)N3;
    float* P1 = S + 8 * (size_t)N3;
    float* Rp1 = S + 9 * (size_t)N3;     // 64^3
    float* Rp2 = Rp1 + 262144;           // 32^3
    float* W32 = Rp2 + 32768;            // 32^3
    float* Rp3 = W32 + 32768;            // 16^3
    float* W16 = Rp3 + 4096;             // 16^3

    dim3 blkF(32, 4), grdF(1, 32, 128);     // fat kernels, 128 thr
    dim3 blkR(32, 8), grdR(1, 16, 64);      // residual (2 planes/block)
    dim3 grdP(1, 16, 128);                  // full-depth grids with blkR

    k_predictor<<<grdF, blkF>>>(U, V, W_, P, SG, DT, BU, BV, BW);
    k_corrector<<<grdF, blkF>>>(BU, BV, BW, U, V, W_, P, SG, DT, U1, V1, W1);

    // iteration 0 (div fused into residual)
    k_residdiv<<<grdR, blkR>>>(P, U1, V1, W1, DT, B, R0, Rp1);
    k_restrict2<<<512, 512>>>(Rp1, Rp2, Rp3);
    k_coarse16<<<1, 512>>>(Rp3, W16, nullptr);
    k_mg32<<<128, 256>>>(W16, Rp2, W32);
    k_pupdate<<<grdP, blkR>>>(P, W32, Rp1, R0, P1, nullptr);

    // iteration 1
    k_resid<<<grdR, blkR>>>(P1, B, R0, Rp1);
    k_restrict2<<<512, 512>>>(Rp1, Rp2, Rp3);
    k_coarse16<<<1, 512>>>(Rp3, W16, o_r);
    k_mg32<<<128, 256>>>(W16, Rp2, W32);
    k_pupdate<<<grdP, blkR>>>(P1, W32, Rp1, R0, o_p, o_wmg);

    k_final<<<grdP, blkR>>>(U1, V1, W1, o_p, SG, DT, o_u, o_v, o_w);
}